// round 1
// baseline (speedup 1.0000x reference)
#include <cuda_runtime.h>
#include <cstdint>

#define B_ 2
#define S_ 2048
#define D_ 1024
#define H_ 16
#define DK_ 64
#define DV_ 64
#define SEG_ 512
#define SL_ 128
#define L_ 768          // SL + SEG + SL
#define NSEG_ 4

// ---------------- scratch (device globals: allocation-free) ----------------
__device__ float g_kf[(size_t)B_*H_*S_*DK_];
__device__ float g_qf[(size_t)B_*H_*S_*DK_];
__device__ float g_vf[(size_t)B_*H_*S_*DV_];
__device__ float g_kk[(size_t)B_*H_*L_*DK_];
__device__ float g_qq[(size_t)B_*H_*L_*DK_];
__device__ float g_vv[(size_t)B_*H_*L_*DV_];
__device__ float g_att1[(size_t)B_*H_*L_*DV_];
__device__ float g_P [(size_t)B_*H_*L_*L_];
__device__ float g_k2[(size_t)B_*H_*L_*128];
__device__ float g_q2[(size_t)B_*H_*L_*128];
__device__ float g_v2[(size_t)B_*H_*L_*128];
__device__ float g_att2[(size_t)B_*H_*L_*128];
__device__ float g_a2r [(size_t)B_*SEG_*2048];
__device__ float g_a2er[(size_t)B_*SL_*2048];
__device__ float g_stA[(size_t)B_*SL_*D_];
__device__ float g_stB[(size_t)B_*SL_*D_];

// ---------------- batched tiled SGEMM: C = A @ B (or A @ B^T) ----------------
// Tile 64x64, K-tile 16, 256 threads, 4x4 microtile per thread.
// Batch: z = blockIdx.z ; b = z / Hd ; h = z % Hd ; pointers offset by strides.
template<bool TB>
__global__ void __launch_bounds__(256) gemm_k(
    const float* __restrict__ A, const float* __restrict__ Bm, float* __restrict__ C,
    int M, int N, int K, int lda, int ldb, int ldc,
    long long aSB, long long aSH, long long bSB, long long bSH,
    long long cSB, long long cSH, int Hd)
{
    int z = blockIdx.z;
    int b = z / Hd, h = z - b * Hd;
    A  += (size_t)b * aSB + (size_t)h * aSH;
    Bm += (size_t)b * bSB + (size_t)h * bSH;
    C  += (size_t)b * cSB + (size_t)h * cSH;

    __shared__ float As[16][65];
    __shared__ float Bs[16][68];

    int tid = threadIdx.x;
    int tx = tid & 15, ty = tid >> 4;
    int row0 = blockIdx.y * 64;
    int col0 = blockIdx.x * 64;

    float acc[4][4] = {{0,0,0,0},{0,0,0,0},{0,0,0,0},{0,0,0,0}};

    for (int k0 = 0; k0 < K; k0 += 16) {
        #pragma unroll
        for (int i = 0; i < 4; i++) {
            int e = (tid << 2) + i;
            As[e & 15][e >> 4] = A[(size_t)(row0 + (e >> 4)) * lda + k0 + (e & 15)];
        }
        if (!TB) {
            #pragma unroll
            for (int i = 0; i < 4; i++) {
                int e = (tid << 2) + i;
                Bs[e >> 6][e & 63] = Bm[(size_t)(k0 + (e >> 6)) * ldb + col0 + (e & 63)];
            }
        } else {
            #pragma unroll
            for (int i = 0; i < 4; i++) {
                int e = (tid << 2) + i;
                Bs[e & 15][e >> 4] = Bm[(size_t)(col0 + (e >> 4)) * ldb + k0 + (e & 15)];
            }
        }
        __syncthreads();
        #pragma unroll
        for (int kk = 0; kk < 16; kk++) {
            float a[4], bv[4];
            #pragma unroll
            for (int i = 0; i < 4; i++) a[i] = As[kk][(ty << 2) + i];
            #pragma unroll
            for (int j = 0; j < 4; j++) bv[j] = Bs[kk][(tx << 2) + j];
            #pragma unroll
            for (int i = 0; i < 4; i++)
                #pragma unroll
                for (int j = 0; j < 4; j++)
                    acc[i][j] = fmaf(a[i], bv[j], acc[i][j]);
        }
        __syncthreads();
    }
    #pragma unroll
    for (int i = 0; i < 4; i++)
        #pragma unroll
        for (int j = 0; j < 4; j++)
            C[(size_t)(row0 + (ty << 2) + i) * ldc + col0 + (tx << 2) + j] = acc[i][j];
}

// row-wise causal softmax (scale applied here); masked cols set to 0
__global__ void softmax_causal(float* __restrict__ P, float scale)
{
    int row = blockIdx.x;
    int z   = blockIdx.y;
    float* p = P + ((size_t)z * L_ + row) * (size_t)L_;
    int n = row + 1;
    __shared__ float red[256];
    int t = threadIdx.x;

    float m = -1e30f;
    for (int c = t; c < n; c += 256) m = fmaxf(m, p[c] * scale);
    red[t] = m; __syncthreads();
    for (int s = 128; s > 0; s >>= 1) {
        if (t < s) red[t] = fmaxf(red[t], red[t + s]);
        __syncthreads();
    }
    m = red[0]; __syncthreads();

    float sum = 0.f;
    for (int c = t; c < n; c += 256) {
        float e = __expf(p[c] * scale - m);
        p[c] = e; sum += e;
    }
    red[t] = sum; __syncthreads();
    for (int s = 128; s > 0; s >>= 1) {
        if (t < s) red[t] += red[t + s];
        __syncthreads();
    }
    float inv = 1.f / red[0];
    for (int c = t; c < n; c += 256) p[c] *= inv;
    for (int c = n + t; c < L_; c += 256) p[c] = 0.f;
}

// build concatenated [state ; segment ; state] rows (rows [0,SL) pre-filled by GEMM)
__global__ void build_cat(float* __restrict__ dst, const float* __restrict__ full, int segoff)
{
    int idx = blockIdx.x * blockDim.x + threadIdx.x;
    const int total = B_ * H_ * (SEG_ + SL_) * 64;
    if (idx >= total) return;
    int d = idx & 63;
    int t = (idx >> 6) % (SEG_ + SL_);
    int z = idx / ((SEG_ + SL_) * 64);
    if (t < SEG_)
        dst[((size_t)z * L_ + SL_ + t) * 64 + d] = full[((size_t)z * S_ + segoff + t) * 64 + d];
    else
        dst[((size_t)z * L_ + SL_ + t) * 64 + d] = dst[((size_t)z * L_ + (t - SEG_)) * 64 + d];
}

// a2 reshape (B,H,SEG,128) -> (B,512,2048): s2 = h*32 + s/16, d2 = (s%16)*128 + c
__global__ void gather_a2r(float* __restrict__ a2r, const float* __restrict__ att2)
{
    int idx = blockIdx.x * blockDim.x + threadIdx.x;
    const int total = B_ * SEG_ * 2048;
    if (idx >= total) return;
    int d2 = idx & 2047;
    int i  = (idx >> 11) % SEG_;
    int b  = idx / (SEG_ * 2048);
    int h = i >> 5, g = i & 31;
    int r = d2 >> 7, c = d2 & 127;
    int s = g * 16 + r;
    a2r[idx] = att2[(((size_t)(b * H_ + h)) * L_ + SL_ + s) * 128 + c];
}

// a2e reshape (B,H,128,128) -> (B,128,2048): s2 = h*8 + s/16
__global__ void gather_a2er(float* __restrict__ a2er, const float* __restrict__ att2)
{
    int idx = blockIdx.x * blockDim.x + threadIdx.x;
    const int total = B_ * SL_ * 2048;
    if (idx >= total) return;
    int d2 = idx & 2047;
    int i  = (idx >> 11) % SL_;
    int b  = idx / (SL_ * 2048);
    int h = i >> 3, g = i & 7;
    int r = d2 >> 7, c = d2 & 127;
    int s = g * 16 + r;
    a2er[idx] = att2[(((size_t)(b * H_ + h)) * L_ + (SL_ + SEG_) + s) * 128 + c];
}

__global__ void bcast_state(float* __restrict__ st, const float* __restrict__ state)
{
    int idx = blockIdx.x * blockDim.x + threadIdx.x;
    const int total = B_ * SL_ * D_;
    if (idx >= total) return;
    st[idx] = state[idx % (SL_ * D_)];
}

__global__ void copy_f(float* __restrict__ dst, const float* __restrict__ src, int n)
{
    int idx = blockIdx.x * blockDim.x + threadIdx.x;
    if (idx < n) dst[idx] = src[idx];
}

// ---------------- host ----------------
static inline void G(bool tb, const float* A, const float* Bm, float* C,
                     int M, int N, int K, int lda, int ldb, int ldc,
                     long long aSB, long long aSH, long long bSB, long long bSH,
                     long long cSB, long long cSH, int Hd, int Z)
{
    dim3 grid(N / 64, M / 64, Z), blk(256);
    if (tb) gemm_k<true ><<<grid, blk>>>(A, Bm, C, M, N, K, lda, ldb, ldc, aSB, aSH, bSB, bSH, cSB, cSH, Hd);
    else    gemm_k<false><<<grid, blk>>>(A, Bm, C, M, N, K, lda, ldb, ldc, aSB, aSH, bSB, bSH, cSB, cSH, Hd);
}

extern "C" void kernel_launch(void* const* d_in, const int* in_sizes, int n_in,
                              void* d_out, int out_size)
{
    const float* x       = (const float*)d_in[0];
    const float* state   = (const float*)d_in[1];
    const float* Wk      = (const float*)d_in[2];
    const float* Wq      = (const float*)d_in[3];
    const float* Wv      = (const float*)d_in[4];
    const float* W2k     = (const float*)d_in[5];
    const float* Wout    = (const float*)d_in[6];
    const float* Wk_st   = (const float*)d_in[7];
    const float* Wq_st   = (const float*)d_in[8];
    const float* Wv_st   = (const float*)d_in[9];
    const float* W2k_ss  = (const float*)d_in[10];
    const float* W2q_ss  = (const float*)d_in[11];
    const float* W2v_ss  = (const float*)d_in[12];
    const float* W2k_se  = (const float*)d_in[13];
    const float* W2q_se  = (const float*)d_in[14];
    const float* W2v_se  = (const float*)d_in[15];
    const float* Wout_st = (const float*)d_in[16];
    float* out = (float*)d_out;

    float *kf,*qf,*vf,*kkb,*qqb,*vvb,*att1,*P,*k2,*q2,*v2,*att2,*a2r,*a2er,*stA,*stB;
    cudaGetSymbolAddress((void**)&kf,  g_kf);
    cudaGetSymbolAddress((void**)&qf,  g_qf);
    cudaGetSymbolAddress((void**)&vf,  g_vf);
    cudaGetSymbolAddress((void**)&kkb, g_kk);
    cudaGetSymbolAddress((void**)&qqb, g_qq);
    cudaGetSymbolAddress((void**)&vvb, g_vv);
    cudaGetSymbolAddress((void**)&att1,g_att1);
    cudaGetSymbolAddress((void**)&P,   g_P);
    cudaGetSymbolAddress((void**)&k2,  g_k2);
    cudaGetSymbolAddress((void**)&q2,  g_q2);
    cudaGetSymbolAddress((void**)&v2,  g_v2);
    cudaGetSymbolAddress((void**)&att2,g_att2);
    cudaGetSymbolAddress((void**)&a2r, g_a2r);
    cudaGetSymbolAddress((void**)&a2er,g_a2er);
    cudaGetSymbolAddress((void**)&stA, g_stA);
    cudaGetSymbolAddress((void**)&stB, g_stB);

    // st0 = broadcast(state)
    bcast_state<<<(B_*SL_*D_ + 255)/256, 256>>>(stA, state);

    // full-sequence projections: per (b,h)  (S x D) @ (D x 64)
    G(false, x, Wk, kf, S_, DK_, D_, D_, DK_, DK_,
      (long long)S_*D_, 0, 0, (long long)D_*DK_,
      (long long)H_*S_*DK_, (long long)S_*DK_, H_, B_*H_);
    G(false, x, Wq, qf, S_, DK_, D_, D_, DK_, DK_,
      (long long)S_*D_, 0, 0, (long long)D_*DK_,
      (long long)H_*S_*DK_, (long long)S_*DK_, H_, B_*H_);
    G(false, x, Wv, vf, S_, DV_, D_, D_, DV_, DV_,
      (long long)S_*D_, 0, 0, (long long)D_*DV_,
      (long long)H_*S_*DV_, (long long)S_*DV_, H_, B_*H_);

    for (int seg = 0; seg < NSEG_; seg++) {
        float* stc = (seg & 1) ? stB : stA;
        float* stn = (seg & 1) ? stA : stB;

        // state projections -> rows [0,SL) of kk/qq/vv
        G(false, stc, Wk_st, kkb, SL_, DK_, D_, D_, DK_, DK_,
          (long long)SL_*D_, 0, 0, (long long)D_*DK_,
          (long long)H_*L_*DK_, (long long)L_*DK_, H_, B_*H_);
        G(false, stc, Wq_st, qqb, SL_, DK_, D_, D_, DK_, DK_,
          (long long)SL_*D_, 0, 0, (long long)D_*DK_,
          (long long)H_*L_*DK_, (long long)L_*DK_, H_, B_*H_);
        G(false, stc, Wv_st, vvb, SL_, DV_, D_, D_, DV_, DV_,
          (long long)SL_*D_, 0, 0, (long long)D_*DV_,
          (long long)H_*L_*DV_, (long long)L_*DV_, H_, B_*H_);

        int ncat = B_ * H_ * (SEG_ + SL_) * 64;
        build_cat<<<(ncat + 255)/256, 256>>>(kkb, kf, seg*SEG_);
        build_cat<<<(ncat + 255)/256, 256>>>(qqb, qf, seg*SEG_);
        build_cat<<<(ncat + 255)/256, 256>>>(vvb, vf, seg*SEG_);

        // attention 1: scores -> softmax -> AV
        G(true, qqb, kkb, P, L_, L_, DK_, DK_, DK_, L_,
          (long long)H_*L_*DK_, (long long)L_*DK_,
          (long long)H_*L_*DK_, (long long)L_*DK_,
          (long long)H_*L_*L_,  (long long)L_*L_, H_, B_*H_);
        softmax_causal<<<dim3(L_, B_*H_), 256>>>(P, 0.125f);
        G(false, P, vvb, att1, L_, DV_, L_, L_, DV_, DV_,
          (long long)H_*L_*L_,  (long long)L_*L_,
          (long long)H_*L_*DV_, (long long)L_*DV_,
          (long long)H_*L_*DV_, (long long)L_*DV_, H_, B_*H_);

        // second-level projections (NOTE: middle uses W2k for k2, q2 AND v2, per reference)
        struct Part { int off, M; const float *wk, *wq, *wv; };
        Part parts[3] = {
            {0,         SL_,  W2k_ss, W2q_ss, W2v_ss},
            {SL_,       SEG_, W2k,    W2k,    W2k   },
            {SL_+SEG_,  SL_,  W2k_se, W2q_se, W2v_se}
        };
        float* dsts[3] = {k2, q2, v2};
        for (int p = 0; p < 3; p++) {
            const float* ws[3] = {parts[p].wk, parts[p].wq, parts[p].wv};
            for (int o = 0; o < 3; o++) {
                G(false, att1 + (size_t)parts[p].off * DV_, ws[o],
                  dsts[o] + (size_t)parts[p].off * 128,
                  parts[p].M, 128, DV_, DV_, 128, 128,
                  (long long)H_*L_*DV_, (long long)L_*DV_,
                  0, (long long)DV_*128,
                  (long long)H_*L_*128, (long long)L_*128, H_, B_*H_);
            }
        }

        // attention 2 (head dim 128, same 1/8 scale)
        G(true, q2, k2, P, L_, L_, 128, 128, 128, L_,
          (long long)H_*L_*128, (long long)L_*128,
          (long long)H_*L_*128, (long long)L_*128,
          (long long)H_*L_*L_,  (long long)L_*L_, H_, B_*H_);
        softmax_causal<<<dim3(L_, B_*H_), 256>>>(P, 0.125f);
        G(false, P, v2, att2, L_, 128, L_, L_, 128, 128,
          (long long)H_*L_*L_,  (long long)L_*L_,
          (long long)H_*L_*128, (long long)L_*128,
          (long long)H_*L_*128, (long long)L_*128, H_, B_*H_);

        // reshapes
        gather_a2r <<<(B_*SEG_*2048 + 255)/256, 256>>>(a2r,  att2);
        gather_a2er<<<(B_*SL_ *2048 + 255)/256, 256>>>(a2er, att2);

        // out segment: (512 x 2048) @ (2048 x 1024), batched over b
        G(false, a2r, Wout, out + (size_t)seg*SEG_*D_, SEG_, D_, 2048, 2048, D_, D_,
          (long long)SEG_*2048, 0, 0, 0, (long long)S_*D_, 0, 1, B_);
        // next state: (128 x 2048) @ (2048 x 1024)
        G(false, a2er, Wout_st, stn, SL_, D_, 2048, 2048, D_, D_,
          (long long)SL_*2048, 0, 0, 0, (long long)SL_*D_, 0, 1, B_);
    }

    // final state lives in stA after 4 segments (3 is odd -> stn == stA)
    int st_elems = B_ * SL_ * D_;
    if (out_size >= B_*S_*D_ + st_elems) {
        copy_f<<<(st_elems + 255)/256, 256>>>(out + (size_t)B_*S_*D_, stA, st_elems);
    }
}

// round 2
// speedup vs baseline: 1.7664x; 1.7664x over previous
#include <cuda_runtime.h>
#include <cstdint>

#define B_ 2
#define S_ 2048
#define D_ 1024
#define H_ 16
#define DK_ 64
#define DV_ 64
#define SEG_ 512
#define SL_ 128
#define L_ 768
#define NSEG_ 4

// ---------------- scratch (device globals: allocation-free) ----------------
__device__ float g_kqvf[(size_t)B_*H_*S_*192];   // full-seq K|Q|V interleaved per row
__device__ float g_cat [(size_t)B_*H_*L_*192];   // concatenated K|Q|V per segment
__device__ float g_att1[(size_t)B_*H_*L_*64];
__device__ float g_P  [(size_t)B_*H_*L_*L_];
__device__ float g_kqv2[(size_t)B_*H_*L_*384];   // k2|q2|v2 interleaved
__device__ float g_att2[(size_t)B_*H_*L_*128];
__device__ float g_a2r [(size_t)B_*SEG_*2048];
__device__ float g_a2er[(size_t)B_*SL_*2048];
__device__ float g_stA[(size_t)B_*SL_*D_];
__device__ float g_stB[(size_t)B_*SL_*D_];
__device__ float g_part[(size_t)4*1024*1024];    // split-K partials
__device__ float g_WkqvF[(size_t)H_*D_*192];     // packed Wk|Wq|Wv
__device__ float g_WstP [(size_t)H_*D_*192];     // packed Wk_st|Wq_st|Wv_st
__device__ float g_W2ss [(size_t)H_*64*384];
__device__ float g_W2mid[(size_t)H_*64*384];
__device__ float g_W2se [(size_t)H_*64*384];

// ---------------- batched tiled SGEMM, double-buffered, 8-wide microtile ----
// C = A @ B (NN) or A @ B^T (TB).  BK=16, 256 threads.
// causal: skip blocks entirely above the diagonal (caller guarantees masked
//         region is overwritten later).  tril: A has zeros for k > row -> clamp K.
// splitK: sk pieces along K, partials written densely, reduced afterwards.
template<int BM, int BN, int TM, int TN, bool TB>
__global__ void __launch_bounds__(256, 2) gemm2(
    const float* __restrict__ A, const float* __restrict__ Bm, float* __restrict__ C,
    int M, int N, int K, int lda, int ldb, int ldc,
    long long aSB, long long aSH, long long bSB, long long bSH,
    long long cSB, long long cSH, int Hd, int Zr,
    int causal, int tril, int sk, int Kc, long long pcs)
{
    constexpr int BK = 16;
    constexpr int TX = BN / TN;

    int z = blockIdx.z;
    int ks = 0, zz = z;
    if (sk > 1) { ks = z / Zr; zz = z - ks * Zr; }
    int b = zz / Hd, h = zz - b * Hd;
    A  += (long long)b * aSB + (long long)h * aSH;
    Bm += (long long)b * bSB + (long long)h * bSH;
    C  += (long long)ks * pcs + (long long)b * cSB + (long long)h * cSH;

    int row0 = blockIdx.y * BM;
    int col0 = blockIdx.x * BN;
    if (causal && col0 >= row0 + BM) return;

    int kBeg = ks * Kc;
    int kEnd = kBeg + Kc;
    if (tril) { int km = row0 + BM; if (km < kEnd) kEnd = km; }
    int nk = (kEnd - kBeg) >> 4;

    __shared__ float As[2][BK][BM + 4];
    __shared__ float Bs[2][BK][BN + 4];

    int tid = threadIdx.x;
    int tx = tid % TX, ty = tid / TX;

    constexpr int NA4 = BM * BK / 1024;   // float4 loads per thread for A tile
    constexpr int NB4 = BN * BK / 1024;
    float4 ag[NA4], bg[NB4];

    // ---- prologue: tile 0 straight to smem buf 0 ----
    {
        int kb = kBeg;
        #pragma unroll
        for (int i = 0; i < NA4; i++) {
            int f = tid + i * 256; int r = f >> 2; int kq = f & 3;
            float4 v = *(const float4*)(A + (long long)(row0 + r) * lda + kb + kq * 4);
            As[0][kq*4+0][r] = v.x; As[0][kq*4+1][r] = v.y;
            As[0][kq*4+2][r] = v.z; As[0][kq*4+3][r] = v.w;
        }
        if (!TB) {
            #pragma unroll
            for (int i = 0; i < NB4; i++) {
                int f = tid + i * 256; int kr = f / (BN/4); int nq = f % (BN/4);
                float4 v = *(const float4*)(Bm + (long long)(kb + kr) * ldb + col0 + nq * 4);
                *(float4*)&Bs[0][kr][nq * 4] = v;
            }
        } else {
            #pragma unroll
            for (int i = 0; i < NB4; i++) {
                int f = tid + i * 256; int r = f >> 2; int kq = f & 3;
                float4 v = *(const float4*)(Bm + (long long)(col0 + r) * ldb + kb + kq * 4);
                Bs[0][kq*4+0][r] = v.x; Bs[0][kq*4+1][r] = v.y;
                Bs[0][kq*4+2][r] = v.z; Bs[0][kq*4+3][r] = v.w;
            }
        }
    }
    __syncthreads();

    float acc[TM][TN];
    #pragma unroll
    for (int i = 0; i < TM; i++)
        #pragma unroll
        for (int j = 0; j < TN; j++) acc[i][j] = 0.f;

    int cur = 0;
    for (int t = 0; t < nk; t++) {
        if (t + 1 < nk) {
            int kb = kBeg + (t + 1) * BK;
            #pragma unroll
            for (int i = 0; i < NA4; i++) {
                int f = tid + i * 256; int r = f >> 2; int kq = f & 3;
                ag[i] = *(const float4*)(A + (long long)(row0 + r) * lda + kb + kq * 4);
            }
            if (!TB) {
                #pragma unroll
                for (int i = 0; i < NB4; i++) {
                    int f = tid + i * 256; int kr = f / (BN/4); int nq = f % (BN/4);
                    bg[i] = *(const float4*)(Bm + (long long)(kb + kr) * ldb + col0 + nq * 4);
                }
            } else {
                #pragma unroll
                for (int i = 0; i < NB4; i++) {
                    int f = tid + i * 256; int r = f >> 2; int kq = f & 3;
                    bg[i] = *(const float4*)(Bm + (long long)(col0 + r) * ldb + kb + kq * 4);
                }
            }
        }
        #pragma unroll
        for (int kk = 0; kk < BK; kk++) {
            float a[TM], bv[TN];
            *(float4*)&a[0] = *(float4*)&As[cur][kk][ty * TM];
            if (TM == 8) *(float4*)&a[4] = *(float4*)&As[cur][kk][ty * TM + 4];
            *(float4*)&bv[0] = *(float4*)&Bs[cur][kk][tx * TN];
            if (TN == 8) *(float4*)&bv[4] = *(float4*)&Bs[cur][kk][tx * TN + 4];
            #pragma unroll
            for (int i = 0; i < TM; i++)
                #pragma unroll
                for (int j = 0; j < TN; j++)
                    acc[i][j] = fmaf(a[i], bv[j], acc[i][j]);
        }
        if (t + 1 < nk) {
            int nxt = cur ^ 1;
            #pragma unroll
            for (int i = 0; i < NA4; i++) {
                int f = tid + i * 256; int r = f >> 2; int kq = f & 3;
                As[nxt][kq*4+0][r] = ag[i].x; As[nxt][kq*4+1][r] = ag[i].y;
                As[nxt][kq*4+2][r] = ag[i].z; As[nxt][kq*4+3][r] = ag[i].w;
            }
            if (!TB) {
                #pragma unroll
                for (int i = 0; i < NB4; i++) {
                    int f = tid + i * 256; int kr = f / (BN/4); int nq = f % (BN/4);
                    *(float4*)&Bs[nxt][kr][nq * 4] = bg[i];
                }
            } else {
                #pragma unroll
                for (int i = 0; i < NB4; i++) {
                    int f = tid + i * 256; int r = f >> 2; int kq = f & 3;
                    Bs[nxt][kq*4+0][r] = bg[i].x; Bs[nxt][kq*4+1][r] = bg[i].y;
                    Bs[nxt][kq*4+2][r] = bg[i].z; Bs[nxt][kq*4+3][r] = bg[i].w;
                }
            }
            __syncthreads();
            cur = nxt;
        }
    }

    #pragma unroll
    for (int i = 0; i < TM; i++) {
        long long rb = (long long)(row0 + ty * TM + i) * ldc + col0 + tx * TN;
        *(float4*)(C + rb) = make_float4(acc[i][0], acc[i][1], acc[i][2], acc[i][3]);
        if (TN == 8)
            *(float4*)(C + rb + 4) = make_float4(acc[i][4], acc[i][5], acc[i][6], acc[i][7]);
    }
}

// sum split-K partials into final C (deterministic, no atomics)
__global__ void reduceK(float* __restrict__ C, const float* __restrict__ part,
    int sk, long long chunk, int M, int N, int ldc,
    long long cSB, long long cSH, int Hd)
{
    long long idx = (long long)blockIdx.x * blockDim.x + threadIdx.x;
    if (idx >= chunk) return;
    int n = (int)(idx % N);
    long long t = idx / N;
    int m = (int)(t % M);
    int zz = (int)(t / M);
    int b = zz / Hd, h = zz - b * Hd;
    float s = 0.f;
    for (int i = 0; i < sk; i++) s += part[(long long)i * chunk + idx];
    C[(long long)b * cSB + (long long)h * cSH + (long long)m * ldc + n] = s;
}

// row-wise causal softmax (scale applied here); masked cols written as 0
__global__ void softmax_causal(float* __restrict__ P, float scale)
{
    int row = blockIdx.x;
    int z   = blockIdx.y;
    float* p = P + ((size_t)z * L_ + row) * (size_t)L_;
    int n = row + 1;
    __shared__ float red[256];
    int t = threadIdx.x;

    float m = -1e30f;
    for (int c = t; c < n; c += 256) m = fmaxf(m, p[c] * scale);
    red[t] = m; __syncthreads();
    for (int s = 128; s > 0; s >>= 1) {
        if (t < s) red[t] = fmaxf(red[t], red[t + s]);
        __syncthreads();
    }
    m = red[0]; __syncthreads();

    float sum = 0.f;
    for (int c = t; c < n; c += 256) {
        float e = __expf(p[c] * scale - m);
        p[c] = e; sum += e;
    }
    red[t] = sum; __syncthreads();
    for (int s = 128; s > 0; s >>= 1) {
        if (t < s) red[t] += red[t + s];
        __syncthreads();
    }
    float inv = 1.f / red[0];
    for (int c = t; c < n; c += 256) p[c] *= inv;
    for (int c = n + t; c < L_; c += 256) p[c] = 0.f;
}

// pack three (n, w) matrices column-wise into (n, 3w)
__global__ void pack3(float* __restrict__ dst, const float* __restrict__ s0,
                      const float* __restrict__ s1, const float* __restrict__ s2,
                      int n, int w)
{
    int idx = blockIdx.x * blockDim.x + threadIdx.x;
    int tot = n * 3 * w;
    if (idx >= tot) return;
    int c = idx % w; int o = (idx / w) % 3; int i = idx / (3 * w);
    const float* s = (o == 0) ? s0 : ((o == 1) ? s1 : s2);
    dst[idx] = s[(size_t)i * w + c];
}

// fill rows [SL, L) of the interleaved cat buffer: segment rows from full
// interleaved projections, then tail state rows copied from rows [0, SL)
__global__ void build_cat(float* __restrict__ dst, const float* __restrict__ full, int segoff)
{
    int idx = blockIdx.x * blockDim.x + threadIdx.x;
    const int total = B_ * H_ * (SEG_ + SL_) * 192;
    if (idx >= total) return;
    int d = idx % 192;
    int t = (idx / 192) % (SEG_ + SL_);
    int z = idx / ((SEG_ + SL_) * 192);
    if (t < SEG_)
        dst[((size_t)z * L_ + SL_ + t) * 192 + d] = full[((size_t)z * S_ + segoff + t) * 192 + d];
    else
        dst[((size_t)z * L_ + SL_ + t) * 192 + d] = dst[((size_t)z * L_ + (t - SEG_)) * 192 + d];
}

__global__ void gather_a2r(float* __restrict__ a2r, const float* __restrict__ att2)
{
    int idx = blockIdx.x * blockDim.x + threadIdx.x;
    const int total = B_ * SEG_ * 2048;
    if (idx >= total) return;
    int d2 = idx & 2047;
    int i  = (idx >> 11) % SEG_;
    int b  = idx / (SEG_ * 2048);
    int h = i >> 5, g = i & 31;
    int r = d2 >> 7, c = d2 & 127;
    int s = g * 16 + r;
    a2r[idx] = att2[(((size_t)(b * H_ + h)) * L_ + SL_ + s) * 128 + c];
}

__global__ void gather_a2er(float* __restrict__ a2er, const float* __restrict__ att2)
{
    int idx = blockIdx.x * blockDim.x + threadIdx.x;
    const int total = B_ * SL_ * 2048;
    if (idx >= total) return;
    int d2 = idx & 2047;
    int i  = (idx >> 11) % SL_;
    int b  = idx / (SL_ * 2048);
    int h = i >> 3, g = i & 7;
    int r = d2 >> 7, c = d2 & 127;
    int s = g * 16 + r;
    a2er[idx] = att2[(((size_t)(b * H_ + h)) * L_ + (SL_ + SEG_) + s) * 128 + c];
}

__global__ void bcast_state(float* __restrict__ st, const float* __restrict__ state)
{
    int idx = blockIdx.x * blockDim.x + threadIdx.x;
    const int total = B_ * SL_ * D_;
    if (idx >= total) return;
    st[idx] = state[idx % (SL_ * D_)];
}

__global__ void copy_f(float* __restrict__ dst, const float* __restrict__ src, int n)
{
    int idx = blockIdx.x * blockDim.x + threadIdx.x;
    if (idx < n) dst[idx] = src[idx];
}

// ---------------- host ----------------
static float* s_part = nullptr;

static void G(bool tb, const float* A, const float* Bm, float* C,
              int M, int N, int K, int lda, int ldb, int ldc,
              long long aSB, long long aSH, long long bSB, long long bSH,
              long long cSB, long long cSH, int Hd, int Z,
              int causal = 0, int tril = 0, int sk = 1)
{
    int Kc = K / sk;
    long long pcs = 0;
    float* Cout = C;
    long long csb = cSB, csh = cSH;
    int ldc2 = ldc;
    if (sk > 1) {
        pcs = (long long)Z * M * N;
        Cout = s_part; ldc2 = N;
        csh = (long long)M * N;
        csb = (long long)Hd * M * N;
    }
    dim3 blk(256);
    if (N % 128 == 0) {
        dim3 grid(N / 128, M / 128, Z * sk);
        if (tb) gemm2<128,128,8,8,true ><<<grid, blk>>>(A, Bm, Cout, M, N, K, lda, ldb, ldc2,
            aSB, aSH, bSB, bSH, csb, csh, Hd, Z, causal, tril, sk, Kc, pcs);
        else    gemm2<128,128,8,8,false><<<grid, blk>>>(A, Bm, Cout, M, N, K, lda, ldb, ldc2,
            aSB, aSH, bSB, bSH, csb, csh, Hd, Z, causal, tril, sk, Kc, pcs);
    } else {
        dim3 grid(N / 64, M / 128, Z * sk);
        if (tb) gemm2<128,64,8,4,true ><<<grid, blk>>>(A, Bm, Cout, M, N, K, lda, ldb, ldc2,
            aSB, aSH, bSB, bSH, csb, csh, Hd, Z, causal, tril, sk, Kc, pcs);
        else    gemm2<128,64,8,4,false><<<grid, blk>>>(A, Bm, Cout, M, N, K, lda, ldb, ldc2,
            aSB, aSH, bSB, bSH, csb, csh, Hd, Z, causal, tril, sk, Kc, pcs);
    }
    if (sk > 1) {
        long long chunk = (long long)Z * M * N;
        reduceK<<<(unsigned)((chunk + 255) / 256), 256>>>(C, s_part, sk, chunk,
            M, N, ldc, cSB, cSH, Hd);
    }
}

extern "C" void kernel_launch(void* const* d_in, const int* in_sizes, int n_in,
                              void* d_out, int out_size)
{
    const float* x       = (const float*)d_in[0];
    const float* state   = (const float*)d_in[1];
    const float* Wk      = (const float*)d_in[2];
    const float* Wq      = (const float*)d_in[3];
    const float* Wv      = (const float*)d_in[4];
    const float* W2k     = (const float*)d_in[5];
    const float* Wout    = (const float*)d_in[6];
    const float* Wk_st   = (const float*)d_in[7];
    const float* Wq_st   = (const float*)d_in[8];
    const float* Wv_st   = (const float*)d_in[9];
    const float* W2k_ss  = (const float*)d_in[10];
    const float* W2q_ss  = (const float*)d_in[11];
    const float* W2v_ss  = (const float*)d_in[12];
    const float* W2k_se  = (const float*)d_in[13];
    const float* W2q_se  = (const float*)d_in[14];
    const float* W2v_se  = (const float*)d_in[15];
    const float* Wout_st = (const float*)d_in[16];
    float* out = (float*)d_out;

    float *kqvf,*cat,*att1,*P,*kqv2,*att2,*a2r,*a2er,*stA,*stB;
    float *WkqvF,*WstP,*W2ss,*W2mid,*W2se;
    cudaGetSymbolAddress((void**)&kqvf, g_kqvf);
    cudaGetSymbolAddress((void**)&cat,  g_cat);
    cudaGetSymbolAddress((void**)&att1, g_att1);
    cudaGetSymbolAddress((void**)&P,    g_P);
    cudaGetSymbolAddress((void**)&kqv2, g_kqv2);
    cudaGetSymbolAddress((void**)&att2, g_att2);
    cudaGetSymbolAddress((void**)&a2r,  g_a2r);
    cudaGetSymbolAddress((void**)&a2er, g_a2er);
    cudaGetSymbolAddress((void**)&stA,  g_stA);
    cudaGetSymbolAddress((void**)&stB,  g_stB);
    cudaGetSymbolAddress((void**)&s_part, g_part);
    cudaGetSymbolAddress((void**)&WkqvF, g_WkqvF);
    cudaGetSymbolAddress((void**)&WstP,  g_WstP);
    cudaGetSymbolAddress((void**)&W2ss,  g_W2ss);
    cudaGetSymbolAddress((void**)&W2mid, g_W2mid);
    cudaGetSymbolAddress((void**)&W2se,  g_W2se);

    // ---- startup: state broadcast + weight packing + fused full projection ----
    bcast_state<<<(B_*SL_*D_ + 255)/256, 256>>>(stA, state);
    pack3<<<(H_*D_*192 + 255)/256, 256>>>(WkqvF, Wk, Wq, Wv, H_*D_, 64);
    pack3<<<(H_*D_*192 + 255)/256, 256>>>(WstP, Wk_st, Wq_st, Wv_st, H_*D_, 64);
    pack3<<<(H_*64*384 + 255)/256, 256>>>(W2ss,  W2k_ss, W2q_ss, W2v_ss, H_*64, 128);
    pack3<<<(H_*64*384 + 255)/256, 256>>>(W2mid, W2k,    W2k,    W2k,    H_*64, 128);
    pack3<<<(H_*64*384 + 255)/256, 256>>>(W2se,  W2k_se, W2q_se, W2v_se, H_*64, 128);

    // full-sequence K|Q|V projection: per (b,h) (2048 x 1024) @ (1024 x 192)
    G(false, x, WkqvF, kqvf, S_, 192, D_, D_, 192, 192,
      (long long)S_*D_, 0, 0, (long long)D_*192,
      (long long)H_*S_*192, (long long)S_*192, H_, B_*H_);

    for (int seg = 0; seg < NSEG_; seg++) {
        float* stc = (seg & 1) ? stB : stA;
        float* stn = (seg & 1) ? stA : stB;

        // state K|Q|V projection -> rows [0,SL) of cat (split-K x2 for occupancy)
        G(false, stc, WstP, cat, SL_, 192, D_, D_, 192, 192,
          (long long)SL_*D_, 0, 0, (long long)D_*192,
          (long long)H_*L_*192, (long long)L_*192, H_, B_*H_, 0, 0, 2);

        int ncat = B_ * H_ * (SEG_ + SL_) * 192;
        build_cat<<<(ncat + 255)/256, 256>>>(cat, kqvf, seg * SEG_);

        // attention 1: scores (causal-skip) -> softmax -> AV (tril-clamped K)
        G(true, cat + 64, cat + 0, P, L_, L_, DK_, 192, 192, L_,
          (long long)H_*L_*192, (long long)L_*192,
          (long long)H_*L_*192, (long long)L_*192,
          (long long)H_*L_*L_,  (long long)L_*L_, H_, B_*H_, 1, 0);
        softmax_causal<<<dim3(L_, B_*H_), 256>>>(P, 0.125f);
        G(false, P, cat + 128, att1, L_, DV_, L_, L_, 192, DV_,
          (long long)H_*L_*L_,  (long long)L_*L_,
          (long long)H_*L_*192, (long long)L_*192,
          (long long)H_*L_*DV_, (long long)L_*DV_, H_, B_*H_, 0, 1);

        // second-level projections (packed k2|q2|v2; middle uses W2k for all three)
        G(false, att1, W2ss, kqv2, SL_, 384, DV_, DV_, 384, 384,
          (long long)H_*L_*DV_, (long long)L_*DV_, 0, (long long)64*384,
          (long long)H_*L_*384, (long long)L_*384, H_, B_*H_);
        G(false, att1 + (size_t)SL_*DV_, W2mid, kqv2 + (size_t)SL_*384,
          SEG_, 384, DV_, DV_, 384, 384,
          (long long)H_*L_*DV_, (long long)L_*DV_, 0, (long long)64*384,
          (long long)H_*L_*384, (long long)L_*384, H_, B_*H_);
        G(false, att1 + (size_t)(SL_+SEG_)*DV_, W2se, kqv2 + (size_t)(SL_+SEG_)*384,
          SL_, 384, DV_, DV_, 384, 384,
          (long long)H_*L_*DV_, (long long)L_*DV_, 0, (long long)64*384,
          (long long)H_*L_*384, (long long)L_*384, H_, B_*H_);

        // attention 2 (head dim 128)
        G(true, kqv2 + 128, kqv2 + 0, P, L_, L_, 128, 384, 384, L_,
          (long long)H_*L_*384, (long long)L_*384,
          (long long)H_*L_*384, (long long)L_*384,
          (long long)H_*L_*L_,  (long long)L_*L_, H_, B_*H_, 1, 0);
        softmax_causal<<<dim3(L_, B_*H_), 256>>>(P, 0.125f);
        G(false, P, kqv2 + 256, att2, L_, 128, L_, L_, 384, 128,
          (long long)H_*L_*L_,  (long long)L_*L_,
          (long long)H_*L_*384, (long long)L_*384,
          (long long)H_*L_*128, (long long)L_*128, H_, B_*H_, 0, 1);

        // reshapes
        gather_a2r <<<(B_*SEG_*2048 + 255)/256, 256>>>(a2r,  att2);
        gather_a2er<<<(B_*SL_ *2048 + 255)/256, 256>>>(a2er, att2);

        // out segment: (512 x 2048) @ (2048 x 1024), split-K x2
        G(false, a2r, Wout, out + (size_t)seg*SEG_*D_, SEG_, D_, 2048, 2048, D_, D_,
          (long long)SEG_*2048, 0, 0, 0, (long long)S_*D_, 0, 1, B_, 0, 0, 2);
        // next state: (128 x 2048) @ (2048 x 1024), split-K x8
        G(false, a2er, Wout_st, stn, SL_, D_, 2048, 2048, D_, D_,
          (long long)SL_*2048, 0, 0, 0, (long long)SL_*D_, 0, 1, B_, 0, 0, 8);
    }

    int st_elems = B_ * SL_ * D_;
    if (out_size >= B_*S_*D_ + st_elems) {
        copy_f<<<(st_elems + 255)/256, 256>>>(out + (size_t)B_*S_*D_, stA, st_elems);
    }
}

// round 4
// speedup vs baseline: 2.4303x; 1.3759x over previous
#include <cuda_runtime.h>
#include <cstdint>

#define B_ 2
#define S_ 2048
#define D_ 1024
#define H_ 16
#define DK_ 64
#define DV_ 64
#define SEG_ 512
#define SL_ 128
#define L_ 768
#define NSEG_ 4

// ---------------- scratch (device globals: allocation-free) ----------------
__device__ float g_kqvf[(size_t)B_*H_*S_*192];
__device__ float g_cat [(size_t)B_*H_*L_*192];
__device__ float g_att1[(size_t)B_*H_*L_*64];
__device__ float g_P  [(size_t)B_*H_*L_*L_];
__device__ float g_kqv2[(size_t)B_*H_*L_*384];
__device__ float g_att2[(size_t)B_*H_*L_*128];
__device__ float g_a2r [(size_t)B_*SEG_*2048];
__device__ float g_a2er[(size_t)B_*SL_*2048];
__device__ float g_stA[(size_t)B_*SL_*D_];
__device__ float g_stB[(size_t)B_*SL_*D_];
__device__ float g_part[(size_t)4*1024*1024];
__device__ float g_WkqvF[(size_t)H_*D_*192];
__device__ float g_WstP [(size_t)H_*D_*192];
__device__ float g_W2ss [(size_t)H_*64*384];
__device__ float g_W2mid[(size_t)H_*64*384];
__device__ float g_W2se [(size_t)H_*64*384];

// ---------------- tf32 helpers ----------------
__device__ __forceinline__ uint32_t f2tf(float f) {
    uint32_t u;
    asm("cvt.rna.tf32.f32 %0, %1;" : "=r"(u) : "f"(f));
    return u;
}
__device__ __forceinline__ void mma8(float* c, const uint32_t* a, const uint32_t* b) {
    asm volatile(
        "mma.sync.aligned.m16n8k8.row.col.f32.tf32.tf32.f32 "
        "{%0,%1,%2,%3}, {%4,%5,%6,%7}, {%8,%9}, {%0,%1,%2,%3};\n"
        : "+f"(c[0]), "+f"(c[1]), "+f"(c[2]), "+f"(c[3])
        : "r"(a[0]), "r"(a[1]), "r"(a[2]), "r"(a[3]), "r"(b[0]), "r"(b[1]));
}
// k-permutation within an 8-block: logical j -> slot; pairs (j, j+4) adjacent
__device__ __forceinline__ int kperm(int k) {
    int j = k & 7;
    return (k & ~7) + ((j < 4) ? (j << 1) : ((j << 1) - 7));
}

// ---------------- batched strided tf32 tensor-core GEMM ----------------
// C = A @ B (NN) or A @ B^T (TB). BK=16, 256 threads, smem double-buffered.
// causal: skip tiles fully above diagonal. tril: clamp K at row0+BM.
// splitK: sk chunks along K -> dense partials, reduced by reduceK.
template<int BM, int BN, int WM, int WN, bool TB>
__global__ void __launch_bounds__(256) gemm_t(
    const float* __restrict__ A, const float* __restrict__ Bm, float* __restrict__ C,
    int M, int N, int K, int lda, int ldb, int ldc,
    long long aSB, long long aSH, long long bSB, long long bSH,
    long long cSB, long long cSH, int Hd, int Zr,
    int causal, int tril, int sk, int Kc, long long pcs)
{
    constexpr int BK = 16;
    constexpr int KS = BK / 8;                  // k8-steps per tile
    constexpr int MF = WM / 16;
    constexpr int NF = WN / 8;
    constexpr int WCOL = BN / WN;               // warps along N
    constexpr int NA4 = BM * BK / 1024;         // float4 loads/thread for A tile
    constexpr int NB4 = BN * BK / 1024;
    constexpr int KQ = BK / 4;                  // float4 per row of A tile

    int z = blockIdx.z;
    int ks = 0, zz = z;
    if (sk > 1) { ks = z / Zr; zz = z - ks * Zr; }
    int b = zz / Hd, h = zz - b * Hd;
    A  += (long long)b * aSB + (long long)h * aSH;
    Bm += (long long)b * bSB + (long long)h * bSH;
    C  += (long long)ks * pcs + (long long)b * cSB + (long long)h * cSH;

    int row0 = blockIdx.y * BM;
    int col0 = blockIdx.x * BN;
    if (causal && col0 >= row0 + BM) return;

    int kBeg = ks * Kc;
    int kEnd = kBeg + Kc;
    if (tril) { int km = row0 + BM; if (km < kEnd) kEnd = km; }
    int nk = (kEnd - kBeg) / BK;

    __shared__ uint32_t As[2][BM][BK + 4];
    __shared__ uint32_t Bs[2][BN][BK + 4];

    int tid = threadIdx.x;
    int w   = tid >> 5;
    int lane = tid & 31;
    int g = lane >> 2, q = lane & 3;
    int warpM = w / WCOL, warpN = w % WCOL;
    int wr = warpM * WM;
    int wc = warpN * WN;

    float4 ag[NA4], bg[NB4];

    // ---- prologue: tile 0 -> smem buf 0 (tf32 convert + k-perm) ----
    {
        int kb = kBeg;
        #pragma unroll
        for (int i = 0; i < NA4; i++) {
            int f = tid + i * 256; int r = f / KQ; int c4 = (f % KQ) << 2;
            float4 v = *(const float4*)(A + (long long)(row0 + r) * lda + kb + c4);
            As[0][r][kperm(c4+0)] = f2tf(v.x);
            As[0][r][kperm(c4+1)] = f2tf(v.y);
            As[0][r][kperm(c4+2)] = f2tf(v.z);
            As[0][r][kperm(c4+3)] = f2tf(v.w);
        }
        if (!TB) {
            #pragma unroll
            for (int i = 0; i < NB4; i++) {
                int f = tid + i * 256; int kr = f / (BN/4); int n4 = (f % (BN/4)) << 2;
                float4 v = *(const float4*)(Bm + (long long)(kb + kr) * ldb + col0 + n4);
                int kp = kperm(kr);
                Bs[0][n4+0][kp] = f2tf(v.x);
                Bs[0][n4+1][kp] = f2tf(v.y);
                Bs[0][n4+2][kp] = f2tf(v.z);
                Bs[0][n4+3][kp] = f2tf(v.w);
            }
        } else {
            #pragma unroll
            for (int i = 0; i < NB4; i++) {
                int f = tid + i * 256; int r = f / KQ; int c4 = (f % KQ) << 2;
                float4 v = *(const float4*)(Bm + (long long)(col0 + r) * ldb + kb + c4);
                Bs[0][r][kperm(c4+0)] = f2tf(v.x);
                Bs[0][r][kperm(c4+1)] = f2tf(v.y);
                Bs[0][r][kperm(c4+2)] = f2tf(v.z);
                Bs[0][r][kperm(c4+3)] = f2tf(v.w);
            }
        }
    }
    __syncthreads();

    float acc[MF][NF][4];
    #pragma unroll
    for (int i = 0; i < MF; i++)
        #pragma unroll
        for (int j = 0; j < NF; j++)
            #pragma unroll
            for (int e = 0; e < 4; e++) acc[i][j][e] = 0.f;

    int cur = 0;
    for (int t = 0; t < nk; t++) {
        if (t + 1 < nk) {
            int kb = kBeg + (t + 1) * BK;
            #pragma unroll
            for (int i = 0; i < NA4; i++) {
                int f = tid + i * 256; int r = f / KQ; int c4 = (f % KQ) << 2;
                ag[i] = *(const float4*)(A + (long long)(row0 + r) * lda + kb + c4);
            }
            if (!TB) {
                #pragma unroll
                for (int i = 0; i < NB4; i++) {
                    int f = tid + i * 256; int kr = f / (BN/4); int n4 = (f % (BN/4)) << 2;
                    bg[i] = *(const float4*)(Bm + (long long)(kb + kr) * ldb + col0 + n4);
                }
            } else {
                #pragma unroll
                for (int i = 0; i < NB4; i++) {
                    int f = tid + i * 256; int r = f / KQ; int c4 = (f % KQ) << 2;
                    bg[i] = *(const float4*)(Bm + (long long)(col0 + r) * ldb + kb + c4);
                }
            }
        }
        // ---- compute on buffer `cur` ----
        #pragma unroll
        for (int s = 0; s < KS; s++) {
            uint32_t af[MF][4], bf[NF][2];
            #pragma unroll
            for (int i = 0; i < MF; i++) {
                uint2 lo = *(const uint2*)&As[cur][wr + 16*i + g    ][8*s + 2*q];
                uint2 hi = *(const uint2*)&As[cur][wr + 16*i + g + 8][8*s + 2*q];
                af[i][0] = lo.x; af[i][1] = hi.x; af[i][2] = lo.y; af[i][3] = hi.y;
            }
            #pragma unroll
            for (int j = 0; j < NF; j++) {
                uint2 bb = *(const uint2*)&Bs[cur][wc + 8*j + g][8*s + 2*q];
                bf[j][0] = bb.x; bf[j][1] = bb.y;
            }
            #pragma unroll
            for (int i = 0; i < MF; i++)
                #pragma unroll
                for (int j = 0; j < NF; j++)
                    mma8(acc[i][j], af[i], bf[j]);
        }
        if (t + 1 < nk) {
            int nxt = cur ^ 1;
            #pragma unroll
            for (int i = 0; i < NA4; i++) {
                int f = tid + i * 256; int r = f / KQ; int c4 = (f % KQ) << 2;
                As[nxt][r][kperm(c4+0)] = f2tf(ag[i].x);
                As[nxt][r][kperm(c4+1)] = f2tf(ag[i].y);
                As[nxt][r][kperm(c4+2)] = f2tf(ag[i].z);
                As[nxt][r][kperm(c4+3)] = f2tf(ag[i].w);
            }
            if (!TB) {
                #pragma unroll
                for (int i = 0; i < NB4; i++) {
                    int f = tid + i * 256; int kr = f / (BN/4); int n4 = (f % (BN/4)) << 2;
                    int kp = kperm(kr);
                    Bs[nxt][n4+0][kp] = f2tf(bg[i].x);
                    Bs[nxt][n4+1][kp] = f2tf(bg[i].y);
                    Bs[nxt][n4+2][kp] = f2tf(bg[i].z);
                    Bs[nxt][n4+3][kp] = f2tf(bg[i].w);
                }
            } else {
                #pragma unroll
                for (int i = 0; i < NB4; i++) {
                    int f = tid + i * 256; int r = f / KQ; int c4 = (f % KQ) << 2;
                    Bs[nxt][r][kperm(c4+0)] = f2tf(bg[i].x);
                    Bs[nxt][r][kperm(c4+1)] = f2tf(bg[i].y);
                    Bs[nxt][r][kperm(c4+2)] = f2tf(bg[i].z);
                    Bs[nxt][r][kperm(c4+3)] = f2tf(bg[i].w);
                }
            }
            __syncthreads();
            cur = nxt;
        }
    }

    // ---- epilogue ----
    #pragma unroll
    for (int i = 0; i < MF; i++) {
        #pragma unroll
        for (int j = 0; j < NF; j++) {
            int r0 = row0 + wr + 16*i + g;
            int c0 = col0 + wc + 8*j + 2*q;
            *(float2*)(C + (long long)r0 * ldc + c0) = make_float2(acc[i][j][0], acc[i][j][1]);
            *(float2*)(C + (long long)(r0 + 8) * ldc + c0) = make_float2(acc[i][j][2], acc[i][j][3]);
        }
    }
}

// sum split-K partials into final C (deterministic)
__global__ void reduceK(float* __restrict__ C, const float* __restrict__ part,
    int sk, long long chunk, int M, int N, int ldc,
    long long cSB, long long cSH, int Hd)
{
    long long idx = (long long)blockIdx.x * blockDim.x + threadIdx.x;
    if (idx >= chunk) return;
    int n = (int)(idx % N);
    long long t = idx / N;
    int m = (int)(t % M);
    int zz = (int)(t / M);
    int b = zz / Hd, h = zz - b * Hd;
    float s = 0.f;
    for (int i = 0; i < sk; i++) s += part[(long long)i * chunk + idx];
    C[(long long)b * cSB + (long long)h * cSH + (long long)m * ldc + n] = s;
}

// row-wise causal softmax; masked cols written as 0
__global__ void softmax_causal(float* __restrict__ P, float scale)
{
    int row = blockIdx.x;
    int z   = blockIdx.y;
    float* p = P + ((size_t)z * L_ + row) * (size_t)L_;
    int n = row + 1;
    __shared__ float red[256];
    int t = threadIdx.x;

    float m = -1e30f;
    for (int c = t; c < n; c += 256) m = fmaxf(m, p[c] * scale);
    red[t] = m; __syncthreads();
    for (int s = 128; s > 0; s >>= 1) {
        if (t < s) red[t] = fmaxf(red[t], red[t + s]);
        __syncthreads();
    }
    m = red[0]; __syncthreads();

    float sum = 0.f;
    for (int c = t; c < n; c += 256) {
        float e = __expf(p[c] * scale - m);
        p[c] = e; sum += e;
    }
    red[t] = sum; __syncthreads();
    for (int s = 128; s > 0; s >>= 1) {
        if (t < s) red[t] += red[t + s];
        __syncthreads();
    }
    float inv = 1.f / red[0];
    for (int c = t; c < n; c += 256) p[c] *= inv;
    for (int c = n + t; c < L_; c += 256) p[c] = 0.f;
}

__global__ void pack3(float* __restrict__ dst, const float* __restrict__ s0,
                      const float* __restrict__ s1, const float* __restrict__ s2,
                      int n, int w)
{
    int idx = blockIdx.x * blockDim.x + threadIdx.x;
    int tot = n * 3 * w;
    if (idx >= tot) return;
    int c = idx % w; int o = (idx / w) % 3; int i = idx / (3 * w);
    const float* s = (o == 0) ? s0 : ((o == 1) ? s1 : s2);
    dst[idx] = s[(size_t)i * w + c];
}

__global__ void build_cat(float* __restrict__ dst, const float* __restrict__ full, int segoff)
{
    int idx = blockIdx.x * blockDim.x + threadIdx.x;
    const int total = B_ * H_ * (SEG_ + SL_) * 192;
    if (idx >= total) return;
    int d = idx % 192;
    int t = (idx / 192) % (SEG_ + SL_);
    int z = idx / ((SEG_ + SL_) * 192);
    if (t < SEG_)
        dst[((size_t)z * L_ + SL_ + t) * 192 + d] = full[((size_t)z * S_ + segoff + t) * 192 + d];
    else
        dst[((size_t)z * L_ + SL_ + t) * 192 + d] = dst[((size_t)z * L_ + (t - SEG_)) * 192 + d];
}

__global__ void gather_a2r(float* __restrict__ a2r, const float* __restrict__ att2)
{
    int idx = blockIdx.x * blockDim.x + threadIdx.x;
    const int total = B_ * SEG_ * 2048;
    if (idx >= total) return;
    int d2 = idx & 2047;
    int i  = (idx >> 11) % SEG_;
    int b  = idx / (SEG_ * 2048);
    int h = i >> 5, g = i & 31;
    int r = d2 >> 7, c = d2 & 127;
    int s = g * 16 + r;
    a2r[idx] = att2[(((size_t)(b * H_ + h)) * L_ + SL_ + s) * 128 + c];
}

__global__ void gather_a2er(float* __restrict__ a2er, const float* __restrict__ att2)
{
    int idx = blockIdx.x * blockDim.x + threadIdx.x;
    const int total = B_ * SL_ * 2048;
    if (idx >= total) return;
    int d2 = idx & 2047;
    int i  = (idx >> 11) % SL_;
    int b  = idx / (SL_ * 2048);
    int h = i >> 3, g = i & 7;
    int r = d2 >> 7, c = d2 & 127;
    int s = g * 16 + r;
    a2er[idx] = att2[(((size_t)(b * H_ + h)) * L_ + (SL_ + SEG_) + s) * 128 + c];
}

__global__ void bcast_state(float* __restrict__ st, const float* __restrict__ state)
{
    int idx = blockIdx.x * blockDim.x + threadIdx.x;
    const int total = B_ * SL_ * D_;
    if (idx >= total) return;
    st[idx] = state[idx % (SL_ * D_)];
}

__global__ void copy_f(float* __restrict__ dst, const float* __restrict__ src, int n)
{
    int idx = blockIdx.x * blockDim.x + threadIdx.x;
    if (idx < n) dst[idx] = src[idx];
}

// ---------------- host ----------------
static float* s_part = nullptr;

static void G(bool tb, const float* A, const float* Bm, float* C,
              int M, int N, int K, int lda, int ldb, int ldc,
              long long aSB, long long aSH, long long bSB, long long bSH,
              long long cSB, long long cSH, int Hd, int Z,
              int causal = 0, int tril = 0, int sk = 1)
{
    int Kc = K / sk;
    long long pcs = 0;
    float* Cout = C;
    long long csb = cSB, csh = cSH;
    int ldc2 = ldc;
    if (sk > 1) {
        pcs = (long long)Z * M * N;
        Cout = s_part; ldc2 = N;
        csh = (long long)M * N;
        csb = (long long)Hd * M * N;
    }
    dim3 blk(256);
    if (N % 128 == 0) {
        dim3 grid(N / 128, M / 128, Z * sk);
        if (tb) gemm_t<128,128,64,32,true ><<<grid, blk>>>(A, Bm, Cout, M, N, K, lda, ldb, ldc2,
            aSB, aSH, bSB, bSH, csb, csh, Hd, Z, causal, tril, sk, Kc, pcs);
        else    gemm_t<128,128,64,32,false><<<grid, blk>>>(A, Bm, Cout, M, N, K, lda, ldb, ldc2,
            aSB, aSH, bSB, bSH, csb, csh, Hd, Z, causal, tril, sk, Kc, pcs);
    } else {
        dim3 grid(N / 64, M / 128, Z * sk);
        if (tb) gemm_t<128,64,32,32,true ><<<grid, blk>>>(A, Bm, Cout, M, N, K, lda, ldb, ldc2,
            aSB, aSH, bSB, bSH, csb, csh, Hd, Z, causal, tril, sk, Kc, pcs);
        else    gemm_t<128,64,32,32,false><<<grid, blk>>>(A, Bm, Cout, M, N, K, lda, ldb, ldc2,
            aSB, aSH, bSB, bSH, csb, csh, Hd, Z, causal, tril, sk, Kc, pcs);
    }
    if (sk > 1) {
        long long chunk = (long long)Z * M * N;
        reduceK<<<(unsigned)((chunk + 255) / 256), 256>>>(C, s_part, sk, chunk,
            M, N, ldc, cSB, cSH, Hd);
    }
}

extern "C" void kernel_launch(void* const* d_in, const int* in_sizes, int n_in,
                              void* d_out, int out_size)
{
    const float* x       = (const float*)d_in[0];
    const float* state   = (const float*)d_in[1];
    const float* Wk      = (const float*)d_in[2];
    const float* Wq      = (const float*)d_in[3];
    const float* Wv      = (const float*)d_in[4];
    const float* W2k     = (const float*)d_in[5];
    const float* Wout    = (const float*)d_in[6];
    const float* Wk_st   = (const float*)d_in[7];
    const float* Wq_st   = (const float*)d_in[8];
    const float* Wv_st   = (const float*)d_in[9];
    const float* W2k_ss  = (const float*)d_in[10];
    const float* W2q_ss  = (const float*)d_in[11];
    const float* W2v_ss  = (const float*)d_in[12];
    const float* W2k_se  = (const float*)d_in[13];
    const float* W2q_se  = (const float*)d_in[14];
    const float* W2v_se  = (const float*)d_in[15];
    const float* Wout_st = (const float*)d_in[16];
    float* out = (float*)d_out;

    float *kqvf,*cat,*att1,*P,*kqv2,*att2,*a2r,*a2er,*stA,*stB;
    float *WkqvF,*WstP,*W2ss,*W2mid,*W2se;
    cudaGetSymbolAddress((void**)&kqvf, g_kqvf);
    cudaGetSymbolAddress((void**)&cat,  g_cat);
    cudaGetSymbolAddress((void**)&att1, g_att1);
    cudaGetSymbolAddress((void**)&P,    g_P);
    cudaGetSymbolAddress((void**)&kqv2, g_kqv2);
    cudaGetSymbolAddress((void**)&att2, g_att2);
    cudaGetSymbolAddress((void**)&a2r,  g_a2r);
    cudaGetSymbolAddress((void**)&a2er, g_a2er);
    cudaGetSymbolAddress((void**)&stA,  g_stA);
    cudaGetSymbolAddress((void**)&stB,  g_stB);
    cudaGetSymbolAddress((void**)&s_part, g_part);
    cudaGetSymbolAddress((void**)&WkqvF, g_WkqvF);
    cudaGetSymbolAddress((void**)&WstP,  g_WstP);
    cudaGetSymbolAddress((void**)&W2ss,  g_W2ss);
    cudaGetSymbolAddress((void**)&W2mid, g_W2mid);
    cudaGetSymbolAddress((void**)&W2se,  g_W2se);

    bcast_state<<<(B_*SL_*D_ + 255)/256, 256>>>(stA, state);
    pack3<<<(H_*D_*192 + 255)/256, 256>>>(WkqvF, Wk, Wq, Wv, H_*D_, 64);
    pack3<<<(H_*D_*192 + 255)/256, 256>>>(WstP, Wk_st, Wq_st, Wv_st, H_*D_, 64);
    pack3<<<(H_*64*384 + 255)/256, 256>>>(W2ss,  W2k_ss, W2q_ss, W2v_ss, H_*64, 128);
    pack3<<<(H_*64*384 + 255)/256, 256>>>(W2mid, W2k,    W2k,    W2k,    H_*64, 128);
    pack3<<<(H_*64*384 + 255)/256, 256>>>(W2se,  W2k_se, W2q_se, W2v_se, H_*64, 128);

    // full-sequence K|Q|V projection
    G(false, x, WkqvF, kqvf, S_, 192, D_, D_, 192, 192,
      (long long)S_*D_, 0, 0, (long long)D_*192,
      (long long)H_*S_*192, (long long)S_*192, H_, B_*H_);

    for (int seg = 0; seg < NSEG_; seg++) {
        float* stc = (seg & 1) ? stB : stA;
        float* stn = (seg & 1) ? stA : stB;

        // state K|Q|V projection -> rows [0,SL) of cat (split-K x2)
        G(false, stc, WstP, cat, SL_, 192, D_, D_, 192, 192,
          (long long)SL_*D_, 0, 0, (long long)D_*192,
          (long long)H_*L_*192, (long long)L_*192, H_, B_*H_, 0, 0, 2);

        int ncat = B_ * H_ * (SEG_ + SL_) * 192;
        build_cat<<<(ncat + 255)/256, 256>>>(cat, kqvf, seg * SEG_);

        // attention 1
        G(true, cat + 64, cat + 0, P, L_, L_, DK_, 192, 192, L_,
          (long long)H_*L_*192, (long long)L_*192,
          (long long)H_*L_*192, (long long)L_*192,
          (long long)H_*L_*L_,  (long long)L_*L_, H_, B_*H_, 1, 0);
        softmax_causal<<<dim3(L_, B_*H_), 256>>>(P, 0.125f);
        G(false, P, cat + 128, att1, L_, DV_, L_, L_, 192, DV_,
          (long long)H_*L_*L_,  (long long)L_*L_,
          (long long)H_*L_*192, (long long)L_*192,
          (long long)H_*L_*DV_, (long long)L_*DV_, H_, B_*H_, 0, 1);

        // second-level projections (middle uses W2k for all three, per reference)
        G(false, att1, W2ss, kqv2, SL_, 384, DV_, DV_, 384, 384,
          (long long)H_*L_*DV_, (long long)L_*DV_, 0, (long long)64*384,
          (long long)H_*L_*384, (long long)L_*384, H_, B_*H_);
        G(false, att1 + (size_t)SL_*DV_, W2mid, kqv2 + (size_t)SL_*384,
          SEG_, 384, DV_, DV_, 384, 384,
          (long long)H_*L_*DV_, (long long)L_*DV_, 0, (long long)64*384,
          (long long)H_*L_*384, (long long)L_*384, H_, B_*H_);
        G(false, att1 + (size_t)(SL_+SEG_)*DV_, W2se, kqv2 + (size_t)(SL_+SEG_)*384,
          SL_, 384, DV_, DV_, 384, 384,
          (long long)H_*L_*DV_, (long long)L_*DV_, 0, (long long)64*384,
          (long long)H_*L_*384, (long long)L_*384, H_, B_*H_);

        // attention 2
        G(true, kqv2 + 128, kqv2 + 0, P, L_, L_, 128, 384, 384, L_,
          (long long)H_*L_*384, (long long)L_*384,
          (long long)H_*L_*384, (long long)L_*384,
          (long long)H_*L_*L_,  (long long)L_*L_, H_, B_*H_, 1, 0);
        softmax_causal<<<dim3(L_, B_*H_), 256>>>(P, 0.125f);
        G(false, P, kqv2 + 256, att2, L_, 128, L_, L_, 384, 128,
          (long long)H_*L_*L_,  (long long)L_*L_,
          (long long)H_*L_*384, (long long)L_*384,
          (long long)H_*L_*128, (long long)L_*128, H_, B_*H_, 0, 1);

        gather_a2r <<<(B_*SEG_*2048 + 255)/256, 256>>>(a2r,  att2);
        gather_a2er<<<(B_*SL_ *2048 + 255)/256, 256>>>(a2er, att2);

        // out segment (split-K x2)
        G(false, a2r, Wout, out + (size_t)seg*SEG_*D_, SEG_, D_, 2048, 2048, D_, D_,
          (long long)SEG_*2048, 0, 0, 0, (long long)S_*D_, 0, 1, B_, 0, 0, 2);
        // next state (split-K x8)
        G(false, a2er, Wout_st, stn, SL_, D_, 2048, 2048, D_, D_,
          (long long)SL_*2048, 0, 0, 0, (long long)SL_*D_, 0, 1, B_, 0, 0, 8);
    }

    int st_elems = B_ * SL_ * D_;
    if (out_size >= B_*S_*D_ + st_elems) {
        copy_f<<<(st_elems + 255)/256, 256>>>(out + (size_t)B_*S_*D_, stA, st_elems);
    }
}

// round 5
// speedup vs baseline: 2.8875x; 1.1881x over previous
#include <cuda_runtime.h>
#include <cstdint>

#define B_ 2
#define S_ 2048
#define D_ 1024
#define H_ 16
#define DK_ 64
#define DV_ 64
#define SEG_ 512
#define SL_ 128
#define L_ 768
#define NSEG_ 4

// ---------------- scratch (device globals: allocation-free) ----------------
__device__ float g_kqvf[(size_t)B_*H_*S_*192];
__device__ float g_cat [(size_t)B_*H_*L_*192];
__device__ float g_att1[(size_t)B_*H_*L_*64];
__device__ float g_kqv2[(size_t)B_*H_*L_*384];
__device__ float g_a2r [(size_t)B_*SEG_*2048];
__device__ float g_a2er[(size_t)B_*SL_*2048];
__device__ float g_stA[(size_t)B_*SL_*D_];
__device__ float g_stB[(size_t)B_*SL_*D_];
__device__ float g_part[(size_t)4*1024*1024];
__device__ float g_WkqvF[(size_t)H_*D_*192];
__device__ float g_WstP [(size_t)H_*D_*192];
__device__ float g_W2ss [(size_t)H_*64*384];
__device__ float g_W2mid[(size_t)H_*64*384];
__device__ float g_W2se [(size_t)H_*64*384];

// ---------------- tf32 helpers ----------------
__device__ __forceinline__ uint32_t f2tf(float f) {
    uint32_t u;
    asm("cvt.rna.tf32.f32 %0, %1;" : "=r"(u) : "f"(f));
    return u;
}
__device__ __forceinline__ void mma8(float* c, const uint32_t* a, const uint32_t* b) {
    asm volatile(
        "mma.sync.aligned.m16n8k8.row.col.f32.tf32.tf32.f32 "
        "{%0,%1,%2,%3}, {%4,%5,%6,%7}, {%8,%9}, {%0,%1,%2,%3};\n"
        : "+f"(c[0]), "+f"(c[1]), "+f"(c[2]), "+f"(c[3])
        : "r"(a[0]), "r"(a[1]), "r"(a[2]), "r"(a[3]), "r"(b[0]), "r"(b[1]));
}
// k-permutation within an 8-block: pairs (j, j+4) adjacent -> single LDS.64 frags
__device__ __forceinline__ int kperm(int k) {
    int j = k & 7;
    return (k & ~7) + ((j < 4) ? (j << 1) : ((j << 1) - 7));
}

// ---------------- batched strided tf32 tensor-core GEMM ----------------
template<int BM, int BN, int WM, int WN, bool TB>
__global__ void __launch_bounds__(256) gemm_t(
    const float* __restrict__ A, const float* __restrict__ Bm, float* __restrict__ C,
    int M, int N, int K, int lda, int ldb, int ldc,
    long long aSB, long long aSH, long long bSB, long long bSH,
    long long cSB, long long cSH, int Hd, int Zr,
    int sk, int Kc, long long pcs)
{
    constexpr int BK = 16;
    constexpr int KS = BK / 8;
    constexpr int MF = WM / 16;
    constexpr int NF = WN / 8;
    constexpr int WCOL = BN / WN;
    constexpr int NA4 = BM * BK / 1024;
    constexpr int NB4 = BN * BK / 1024;
    constexpr int KQ = BK / 4;

    int z = blockIdx.z;
    int ks = 0, zz = z;
    if (sk > 1) { ks = z / Zr; zz = z - ks * Zr; }
    int b = zz / Hd, h = zz - b * Hd;
    A  += (long long)b * aSB + (long long)h * aSH;
    Bm += (long long)b * bSB + (long long)h * bSH;
    C  += (long long)ks * pcs + (long long)b * cSB + (long long)h * cSH;

    int row0 = blockIdx.y * BM;
    int col0 = blockIdx.x * BN;

    int kBeg = ks * Kc;
    int nk = Kc / BK;

    __shared__ uint32_t As[2][BM][BK + 4];
    __shared__ uint32_t Bs[2][BN][BK + 4];

    int tid = threadIdx.x;
    int w   = tid >> 5;
    int lane = tid & 31;
    int g = lane >> 2, q = lane & 3;
    int warpM = w / WCOL, warpN = w % WCOL;
    int wr = warpM * WM;
    int wc = warpN * WN;

    float4 ag[NA4], bg[NB4];

    {
        int kb = kBeg;
        #pragma unroll
        for (int i = 0; i < NA4; i++) {
            int f = tid + i * 256; int r = f / KQ; int c4 = (f % KQ) << 2;
            float4 v = *(const float4*)(A + (long long)(row0 + r) * lda + kb + c4);
            As[0][r][kperm(c4+0)] = f2tf(v.x);
            As[0][r][kperm(c4+1)] = f2tf(v.y);
            As[0][r][kperm(c4+2)] = f2tf(v.z);
            As[0][r][kperm(c4+3)] = f2tf(v.w);
        }
        if (!TB) {
            #pragma unroll
            for (int i = 0; i < NB4; i++) {
                int f = tid + i * 256; int kr = f / (BN/4); int n4 = (f % (BN/4)) << 2;
                float4 v = *(const float4*)(Bm + (long long)(kb + kr) * ldb + col0 + n4);
                int kp = kperm(kr);
                Bs[0][n4+0][kp] = f2tf(v.x);
                Bs[0][n4+1][kp] = f2tf(v.y);
                Bs[0][n4+2][kp] = f2tf(v.z);
                Bs[0][n4+3][kp] = f2tf(v.w);
            }
        } else {
            #pragma unroll
            for (int i = 0; i < NB4; i++) {
                int f = tid + i * 256; int r = f / KQ; int c4 = (f % KQ) << 2;
                float4 v = *(const float4*)(Bm + (long long)(col0 + r) * ldb + kb + c4);
                Bs[0][r][kperm(c4+0)] = f2tf(v.x);
                Bs[0][r][kperm(c4+1)] = f2tf(v.y);
                Bs[0][r][kperm(c4+2)] = f2tf(v.z);
                Bs[0][r][kperm(c4+3)] = f2tf(v.w);
            }
        }
    }
    __syncthreads();

    float acc[MF][NF][4];
    #pragma unroll
    for (int i = 0; i < MF; i++)
        #pragma unroll
        for (int j = 0; j < NF; j++)
            #pragma unroll
            for (int e = 0; e < 4; e++) acc[i][j][e] = 0.f;

    int cur = 0;
    for (int t = 0; t < nk; t++) {
        if (t + 1 < nk) {
            int kb = kBeg + (t + 1) * BK;
            #pragma unroll
            for (int i = 0; i < NA4; i++) {
                int f = tid + i * 256; int r = f / KQ; int c4 = (f % KQ) << 2;
                ag[i] = *(const float4*)(A + (long long)(row0 + r) * lda + kb + c4);
            }
            if (!TB) {
                #pragma unroll
                for (int i = 0; i < NB4; i++) {
                    int f = tid + i * 256; int kr = f / (BN/4); int n4 = (f % (BN/4)) << 2;
                    bg[i] = *(const float4*)(Bm + (long long)(kb + kr) * ldb + col0 + n4);
                }
            } else {
                #pragma unroll
                for (int i = 0; i < NB4; i++) {
                    int f = tid + i * 256; int r = f / KQ; int c4 = (f % KQ) << 2;
                    bg[i] = *(const float4*)(Bm + (long long)(col0 + r) * ldb + kb + c4);
                }
            }
        }
        #pragma unroll
        for (int s = 0; s < KS; s++) {
            uint32_t af[MF][4], bf[NF][2];
            #pragma unroll
            for (int i = 0; i < MF; i++) {
                uint2 lo = *(const uint2*)&As[cur][wr + 16*i + g    ][8*s + 2*q];
                uint2 hi = *(const uint2*)&As[cur][wr + 16*i + g + 8][8*s + 2*q];
                af[i][0] = lo.x; af[i][1] = hi.x; af[i][2] = lo.y; af[i][3] = hi.y;
            }
            #pragma unroll
            for (int j = 0; j < NF; j++) {
                uint2 bb = *(const uint2*)&Bs[cur][wc + 8*j + g][8*s + 2*q];
                bf[j][0] = bb.x; bf[j][1] = bb.y;
            }
            #pragma unroll
            for (int i = 0; i < MF; i++)
                #pragma unroll
                for (int j = 0; j < NF; j++)
                    mma8(acc[i][j], af[i], bf[j]);
        }
        if (t + 1 < nk) {
            int nxt = cur ^ 1;
            #pragma unroll
            for (int i = 0; i < NA4; i++) {
                int f = tid + i * 256; int r = f / KQ; int c4 = (f % KQ) << 2;
                As[nxt][r][kperm(c4+0)] = f2tf(ag[i].x);
                As[nxt][r][kperm(c4+1)] = f2tf(ag[i].y);
                As[nxt][r][kperm(c4+2)] = f2tf(ag[i].z);
                As[nxt][r][kperm(c4+3)] = f2tf(ag[i].w);
            }
            if (!TB) {
                #pragma unroll
                for (int i = 0; i < NB4; i++) {
                    int f = tid + i * 256; int kr = f / (BN/4); int n4 = (f % (BN/4)) << 2;
                    int kp = kperm(kr);
                    Bs[nxt][n4+0][kp] = f2tf(bg[i].x);
                    Bs[nxt][n4+1][kp] = f2tf(bg[i].y);
                    Bs[nxt][n4+2][kp] = f2tf(bg[i].z);
                    Bs[nxt][n4+3][kp] = f2tf(bg[i].w);
                }
            } else {
                #pragma unroll
                for (int i = 0; i < NB4; i++) {
                    int f = tid + i * 256; int r = f / KQ; int c4 = (f % KQ) << 2;
                    Bs[nxt][r][kperm(c4+0)] = f2tf(bg[i].x);
                    Bs[nxt][r][kperm(c4+1)] = f2tf(bg[i].y);
                    Bs[nxt][r][kperm(c4+2)] = f2tf(bg[i].z);
                    Bs[nxt][r][kperm(c4+3)] = f2tf(bg[i].w);
                }
            }
            __syncthreads();
            cur = nxt;
        }
    }

    #pragma unroll
    for (int i = 0; i < MF; i++) {
        #pragma unroll
        for (int j = 0; j < NF; j++) {
            int r0 = row0 + wr + 16*i + g;
            int c0 = col0 + wc + 8*j + 2*q;
            *(float2*)(C + (long long)r0 * ldc + c0) = make_float2(acc[i][j][0], acc[i][j][1]);
            *(float2*)(C + (long long)(r0 + 8) * ldc + c0) = make_float2(acc[i][j][2], acc[i][j][3]);
        }
    }
}

// ---------------- fused flash attention (tf32 mma, online softmax) ----------
// BR=128 rows/CTA (8 warps x 16), BC=64 cols/iter, causal, scale=0.125.
// GATHER=0: dense output out0 (ld=DH, bh-stride L*DH).
// GATHER=1: skip rows [0,SL); write gathered a2r/a2er layouts directly.
template<int DH, bool GATHER>
__global__ void __launch_bounds__(256) flash_k(
    const float* __restrict__ base, int ld, long long bhS,
    int qoff, int koff, int voff,
    float* __restrict__ out0, float* __restrict__ out1)
{
    constexpr int BR = 128, BC = 64;
    constexpr int QW = DH + 4, KW = DH + 4, VW = BC + 4, SW = BC + 4;
    extern __shared__ uint32_t sm[];
    uint32_t* Qs = sm;
    uint32_t* Ks = Qs + BR * QW;
    uint32_t* Vs = Ks + BC * KW;
    uint32_t* Ss = Vs + DH * VW;

    int bh = blockIdx.y;
    int b = bh / H_, h = bh - b * H_;
    const float* Qp = base + (long long)bh * bhS + qoff;
    const float* Kp = base + (long long)bh * bhS + koff;
    const float* Vp = base + (long long)bh * bhS + voff;

    int row0 = (GATHER ? (blockIdx.x + 1) : blockIdx.x) * BR;

    int tid = threadIdx.x, w = tid >> 5, lane = tid & 31;
    int g = lane >> 2, q = lane & 3;
    int wr = w * 16;

    // load Q tile once
    constexpr int NQ4 = BR * DH / 1024;
    #pragma unroll
    for (int i = 0; i < NQ4; i++) {
        int f = tid + i * 256; int r = f / (DH/4); int c4 = (f % (DH/4)) << 2;
        float4 v = *(const float4*)(Qp + (long long)(row0 + r) * ld + c4);
        Qs[r*QW + kperm(c4+0)] = f2tf(v.x);
        Qs[r*QW + kperm(c4+1)] = f2tf(v.y);
        Qs[r*QW + kperm(c4+2)] = f2tf(v.z);
        Qs[r*QW + kperm(c4+3)] = f2tf(v.w);
    }

    float Ofr[DH/8][4];
    #pragma unroll
    for (int j = 0; j < DH/8; j++)
        #pragma unroll
        for (int e = 0; e < 4; e++) Ofr[j][e] = 0.f;
    float m_a = -1e30f, m_b = -1e30f, l_a = 0.f, l_b = 0.f;
    int row_a = row0 + wr + g, row_b = row_a + 8;

    int nb = row0 / BC + 2;
    constexpr int NK4 = BC * DH / 1024;

    for (int cb = 0; cb < nb; cb++) {
        int c0 = cb * BC;
        __syncthreads();
        // load K tile (row-major, k-permuted)
        #pragma unroll
        for (int i = 0; i < NK4; i++) {
            int f = tid + i * 256; int r = f / (DH/4); int c4 = (f % (DH/4)) << 2;
            float4 v = *(const float4*)(Kp + (long long)(c0 + r) * ld + c4);
            Ks[r*KW + kperm(c4+0)] = f2tf(v.x);
            Ks[r*KW + kperm(c4+1)] = f2tf(v.y);
            Ks[r*KW + kperm(c4+2)] = f2tf(v.z);
            Ks[r*KW + kperm(c4+3)] = f2tf(v.w);
        }
        // load V tile transposed: Vs[d][kperm(c)]
        #pragma unroll
        for (int i = 0; i < NK4; i++) {
            int f = tid + i * 256; int c = f / (DH/4); int d4 = (f % (DH/4)) << 2;
            float4 v = *(const float4*)(Vp + (long long)(c0 + c) * ld + d4);
            int kp = kperm(c);
            Vs[(d4+0)*VW + kp] = f2tf(v.x);
            Vs[(d4+1)*VW + kp] = f2tf(v.y);
            Vs[(d4+2)*VW + kp] = f2tf(v.z);
            Vs[(d4+3)*VW + kp] = f2tf(v.w);
        }
        __syncthreads();

        // S = Q K^T (per warp: 16 rows x BC cols)
        float sfr[BC/8][4];
        #pragma unroll
        for (int j = 0; j < BC/8; j++)
            #pragma unroll
            for (int e = 0; e < 4; e++) sfr[j][e] = 0.f;
        #pragma unroll
        for (int s = 0; s < DH/8; s++) {
            uint32_t af[4];
            uint2 lo = *(const uint2*)&Qs[(wr+g  )*QW + 8*s + 2*q];
            uint2 hi = *(const uint2*)&Qs[(wr+g+8)*QW + 8*s + 2*q];
            af[0] = lo.x; af[1] = hi.x; af[2] = lo.y; af[3] = hi.y;
            #pragma unroll
            for (int j = 0; j < BC/8; j++) {
                uint2 bb = *(const uint2*)&Ks[(8*j+g)*KW + 8*s + 2*q];
                uint32_t bf[2] = {bb.x, bb.y};
                mma8(sfr[j], af, bf);
            }
        }

        // scale + causal mask + online softmax
        bool needm = (c0 + BC - 1 > row0 + wr);
        float mb_a = -1e30f, mb_b = -1e30f;
        #pragma unroll
        for (int j = 0; j < BC/8; j++) {
            int col = c0 + 8*j + 2*q;
            float s0 = sfr[j][0]*0.125f, s1 = sfr[j][1]*0.125f;
            float s2 = sfr[j][2]*0.125f, s3 = sfr[j][3]*0.125f;
            if (needm) {
                if (col     > row_a) s0 = -1e30f;
                if (col + 1 > row_a) s1 = -1e30f;
                if (col     > row_b) s2 = -1e30f;
                if (col + 1 > row_b) s3 = -1e30f;
            }
            sfr[j][0]=s0; sfr[j][1]=s1; sfr[j][2]=s2; sfr[j][3]=s3;
            mb_a = fmaxf(mb_a, fmaxf(s0, s1));
            mb_b = fmaxf(mb_b, fmaxf(s2, s3));
        }
        mb_a = fmaxf(mb_a, __shfl_xor_sync(0xffffffffu, mb_a, 1));
        mb_a = fmaxf(mb_a, __shfl_xor_sync(0xffffffffu, mb_a, 2));
        mb_b = fmaxf(mb_b, __shfl_xor_sync(0xffffffffu, mb_b, 1));
        mb_b = fmaxf(mb_b, __shfl_xor_sync(0xffffffffu, mb_b, 2));
        float mn_a = fmaxf(m_a, mb_a), mn_b = fmaxf(m_b, mb_b);
        float ra = __expf(m_a - mn_a), rb = __expf(m_b - mn_b);
        float sa = 0.f, sb = 0.f;
        #pragma unroll
        for (int j = 0; j < BC/8; j++) {
            float p0 = __expf(sfr[j][0] - mn_a), p1 = __expf(sfr[j][1] - mn_a);
            float p2 = __expf(sfr[j][2] - mn_b), p3 = __expf(sfr[j][3] - mn_b);
            sa += p0 + p1; sb += p2 + p3;
            int cc = 8*j + 2*q;
            Ss[(wr+g  )*SW + kperm(cc  )] = f2tf(p0);
            Ss[(wr+g  )*SW + kperm(cc+1)] = f2tf(p1);
            Ss[(wr+g+8)*SW + kperm(cc  )] = f2tf(p2);
            Ss[(wr+g+8)*SW + kperm(cc+1)] = f2tf(p3);
        }
        sa += __shfl_xor_sync(0xffffffffu, sa, 1);
        sa += __shfl_xor_sync(0xffffffffu, sa, 2);
        sb += __shfl_xor_sync(0xffffffffu, sb, 1);
        sb += __shfl_xor_sync(0xffffffffu, sb, 2);
        l_a = l_a * ra + sa; l_b = l_b * rb + sb;
        m_a = mn_a; m_b = mn_b;
        #pragma unroll
        for (int j2 = 0; j2 < DH/8; j2++) {
            Ofr[j2][0] *= ra; Ofr[j2][1] *= ra;
            Ofr[j2][2] *= rb; Ofr[j2][3] *= rb;
        }
        __syncwarp();

        // O += P V
        #pragma unroll
        for (int s = 0; s < BC/8; s++) {
            uint32_t af[4];
            uint2 lo = *(const uint2*)&Ss[(wr+g  )*SW + 8*s + 2*q];
            uint2 hi = *(const uint2*)&Ss[(wr+g+8)*SW + 8*s + 2*q];
            af[0] = lo.x; af[1] = hi.x; af[2] = lo.y; af[3] = hi.y;
            #pragma unroll
            for (int j2 = 0; j2 < DH/8; j2++) {
                uint2 bb = *(const uint2*)&Vs[(8*j2+g)*VW + 8*s + 2*q];
                uint32_t bf[2] = {bb.x, bb.y};
                mma8(Ofr[j2], af, bf);
            }
        }
    }

    // epilogue
    float ia = 1.f / l_a, ib = 1.f / l_b;
    if (!GATHER) {
        float* oa = out0 + (long long)bh * L_ * DH + (long long)row_a * DH;
        float* ob = out0 + (long long)bh * L_ * DH + (long long)row_b * DH;
        #pragma unroll
        for (int j2 = 0; j2 < DH/8; j2++) {
            int col = 8*j2 + 2*q;
            *(float2*)(oa + col) = make_float2(Ofr[j2][0]*ia, Ofr[j2][1]*ia);
            *(float2*)(ob + col) = make_float2(Ofr[j2][2]*ib, Ofr[j2][3]*ib);
        }
    } else {
        #pragma unroll
        for (int rr = 0; rr < 2; rr++) {
            int s_abs = (rr == 0) ? row_a : row_b;
            float inv = (rr == 0) ? ia : ib;
            float* dst;
            if (s_abs < SL_ + SEG_) {
                int s = s_abs - SL_;
                int i = (h << 5) + (s >> 4);
                dst = out0 + ((long long)(b * SEG_ + i)) * 2048 + ((s & 15) << 7);
            } else {
                int s = s_abs - (SL_ + SEG_);
                int i = (h << 3) + (s >> 4);
                dst = out1 + ((long long)(b * SL_ + i)) * 2048 + ((s & 15) << 7);
            }
            #pragma unroll
            for (int j2 = 0; j2 < DH/8; j2++) {
                int col = 8*j2 + 2*q;
                float v0 = Ofr[j2][rr ? 2 : 0] * inv;
                float v1 = Ofr[j2][rr ? 3 : 1] * inv;
                *(float2*)(dst + col) = make_float2(v0, v1);
            }
        }
    }
}

// sum split-K partials into final C (deterministic)
__global__ void reduceK(float* __restrict__ C, const float* __restrict__ part,
    int sk, long long chunk, int M, int N, int ldc,
    long long cSB, long long cSH, int Hd)
{
    long long idx = (long long)blockIdx.x * blockDim.x + threadIdx.x;
    if (idx >= chunk) return;
    int n = (int)(idx % N);
    long long t = idx / N;
    int m = (int)(t % M);
    int zz = (int)(t / M);
    int b = zz / Hd, h = zz - b * Hd;
    float s = 0.f;
    for (int i = 0; i < sk; i++) s += part[(long long)i * chunk + idx];
    C[(long long)b * cSB + (long long)h * cSH + (long long)m * ldc + n] = s;
}

__global__ void pack3(float* __restrict__ dst, const float* __restrict__ s0,
                      const float* __restrict__ s1, const float* __restrict__ s2,
                      int n, int w)
{
    int idx = blockIdx.x * blockDim.x + threadIdx.x;
    int tot = n * 3 * w;
    if (idx >= tot) return;
    int c = idx % w; int o = (idx / w) % 3; int i = idx / (3 * w);
    const float* s = (o == 0) ? s0 : ((o == 1) ? s1 : s2);
    dst[idx] = s[(size_t)i * w + c];
}

__global__ void build_cat(float* __restrict__ dst, const float* __restrict__ full, int segoff)
{
    int idx = blockIdx.x * blockDim.x + threadIdx.x;
    const int total = B_ * H_ * (SEG_ + SL_) * 192;
    if (idx >= total) return;
    int d = idx % 192;
    int t = (idx / 192) % (SEG_ + SL_);
    int z = idx / ((SEG_ + SL_) * 192);
    if (t < SEG_)
        dst[((size_t)z * L_ + SL_ + t) * 192 + d] = full[((size_t)z * S_ + segoff + t) * 192 + d];
    else
        dst[((size_t)z * L_ + SL_ + t) * 192 + d] = dst[((size_t)z * L_ + (t - SEG_)) * 192 + d];
}

__global__ void bcast_state(float* __restrict__ st, const float* __restrict__ state)
{
    int idx = blockIdx.x * blockDim.x + threadIdx.x;
    const int total = B_ * SL_ * D_;
    if (idx >= total) return;
    st[idx] = state[idx % (SL_ * D_)];
}

__global__ void copy_f(float* __restrict__ dst, const float* __restrict__ src, int n)
{
    int idx = blockIdx.x * blockDim.x + threadIdx.x;
    if (idx < n) dst[idx] = src[idx];
}

// ---------------- host ----------------
static float* s_part = nullptr;

static void G(bool tb, const float* A, const float* Bm, float* C,
              int M, int N, int K, int lda, int ldb, int ldc,
              long long aSB, long long aSH, long long bSB, long long bSH,
              long long cSB, long long cSH, int Hd, int Z, int sk = 1)
{
    int Kc = K / sk;
    long long pcs = 0;
    float* Cout = C;
    long long csb = cSB, csh = cSH;
    int ldc2 = ldc;
    if (sk > 1) {
        pcs = (long long)Z * M * N;
        Cout = s_part; ldc2 = N;
        csh = (long long)M * N;
        csb = (long long)Hd * M * N;
    }
    dim3 blk(256);
    if (N % 128 == 0) {
        dim3 grid(N / 128, M / 128, Z * sk);
        if (tb) gemm_t<128,128,64,32,true ><<<grid, blk>>>(A, Bm, Cout, M, N, K, lda, ldb, ldc2,
            aSB, aSH, bSB, bSH, csb, csh, Hd, Z, sk, Kc, pcs);
        else    gemm_t<128,128,64,32,false><<<grid, blk>>>(A, Bm, Cout, M, N, K, lda, ldb, ldc2,
            aSB, aSH, bSB, bSH, csb, csh, Hd, Z, sk, Kc, pcs);
    } else {
        dim3 grid(N / 64, M / 128, Z * sk);
        if (tb) gemm_t<128,64,32,32,true ><<<grid, blk>>>(A, Bm, Cout, M, N, K, lda, ldb, ldc2,
            aSB, aSH, bSB, bSH, csb, csh, Hd, Z, sk, Kc, pcs);
        else    gemm_t<128,64,32,32,false><<<grid, blk>>>(A, Bm, Cout, M, N, K, lda, ldb, ldc2,
            aSB, aSH, bSB, bSH, csb, csh, Hd, Z, sk, Kc, pcs);
    }
    if (sk > 1) {
        long long chunk = (long long)Z * M * N;
        reduceK<<<(unsigned)((chunk + 255) / 256), 256>>>(C, s_part, sk, chunk,
            M, N, ldc, cSB, cSH, Hd);
    }
}

extern "C" void kernel_launch(void* const* d_in, const int* in_sizes, int n_in,
                              void* d_out, int out_size)
{
    const float* x       = (const float*)d_in[0];
    const float* state   = (const float*)d_in[1];
    const float* Wk      = (const float*)d_in[2];
    const float* Wq      = (const float*)d_in[3];
    const float* Wv      = (const float*)d_in[4];
    const float* W2k     = (const float*)d_in[5];
    const float* Wout    = (const float*)d_in[6];
    const float* Wk_st   = (const float*)d_in[7];
    const float* Wq_st   = (const float*)d_in[8];
    const float* Wv_st   = (const float*)d_in[9];
    const float* W2k_ss  = (const float*)d_in[10];
    const float* W2q_ss  = (const float*)d_in[11];
    const float* W2v_ss  = (const float*)d_in[12];
    const float* W2k_se  = (const float*)d_in[13];
    const float* W2q_se  = (const float*)d_in[14];
    const float* W2v_se  = (const float*)d_in[15];
    const float* Wout_st = (const float*)d_in[16];
    float* out = (float*)d_out;

    float *kqvf,*cat,*att1,*kqv2,*a2r,*a2er,*stA,*stB;
    float *WkqvF,*WstP,*W2ss,*W2mid,*W2se;
    cudaGetSymbolAddress((void**)&kqvf, g_kqvf);
    cudaGetSymbolAddress((void**)&cat,  g_cat);
    cudaGetSymbolAddress((void**)&att1, g_att1);
    cudaGetSymbolAddress((void**)&kqv2, g_kqv2);
    cudaGetSymbolAddress((void**)&a2r,  g_a2r);
    cudaGetSymbolAddress((void**)&a2er, g_a2er);
    cudaGetSymbolAddress((void**)&stA,  g_stA);
    cudaGetSymbolAddress((void**)&stB,  g_stB);
    cudaGetSymbolAddress((void**)&s_part, g_part);
    cudaGetSymbolAddress((void**)&WkqvF, g_WkqvF);
    cudaGetSymbolAddress((void**)&WstP,  g_WstP);
    cudaGetSymbolAddress((void**)&W2ss,  g_W2ss);
    cudaGetSymbolAddress((void**)&W2mid, g_W2mid);
    cudaGetSymbolAddress((void**)&W2se,  g_W2se);

    // raise dynamic smem limits for flash kernels (idempotent host calls)
    const int SM64  = (128*68 + 64*68 + 64*68 + 128*68) * 4;    // 104448
    const int SM128 = (128*132 + 64*132 + 128*68 + 128*68) * 4; // 171008
    cudaFuncSetAttribute(flash_k<64,false>,  cudaFuncAttributeMaxDynamicSharedMemorySize, SM64);
    cudaFuncSetAttribute(flash_k<128,true>,  cudaFuncAttributeMaxDynamicSharedMemorySize, SM128);

    bcast_state<<<(B_*SL_*D_ + 255)/256, 256>>>(stA, state);
    pack3<<<(H_*D_*192 + 255)/256, 256>>>(WkqvF, Wk, Wq, Wv, H_*D_, 64);
    pack3<<<(H_*D_*192 + 255)/256, 256>>>(WstP, Wk_st, Wq_st, Wv_st, H_*D_, 64);
    pack3<<<(H_*64*384 + 255)/256, 256>>>(W2ss,  W2k_ss, W2q_ss, W2v_ss, H_*64, 128);
    pack3<<<(H_*64*384 + 255)/256, 256>>>(W2mid, W2k,    W2k,    W2k,    H_*64, 128);
    pack3<<<(H_*64*384 + 255)/256, 256>>>(W2se,  W2k_se, W2q_se, W2v_se, H_*64, 128);

    // full-sequence K|Q|V projection
    G(false, x, WkqvF, kqvf, S_, 192, D_, D_, 192, 192,
      (long long)S_*D_, 0, 0, (long long)D_*192,
      (long long)H_*S_*192, (long long)S_*192, H_, B_*H_);

    for (int seg = 0; seg < NSEG_; seg++) {
        float* stc = (seg & 1) ? stB : stA;
        float* stn = (seg & 1) ? stA : stB;

        // state K|Q|V projection -> rows [0,SL) of cat (split-K x2)
        G(false, stc, WstP, cat, SL_, 192, D_, D_, 192, 192,
          (long long)SL_*D_, 0, 0, (long long)D_*192,
          (long long)H_*L_*192, (long long)L_*192, H_, B_*H_, 2);

        int ncat = B_ * H_ * (SEG_ + SL_) * 192;
        build_cat<<<(ncat + 255)/256, 256>>>(cat, kqvf, seg * SEG_);

        // attention 1: fused flash (Q at +64, K at +0, V at +128 in cat)
        flash_k<64,false><<<dim3(L_/128, B_*H_), 256, SM64>>>(
            cat, 192, (long long)L_*192, 64, 0, 128, att1, nullptr);

        // second-level projections (middle uses W2k for all three, per reference)
        G(false, att1, W2ss, kqv2, SL_, 384, DV_, DV_, 384, 384,
          (long long)H_*L_*DV_, (long long)L_*DV_, 0, (long long)64*384,
          (long long)H_*L_*384, (long long)L_*384, H_, B_*H_);
        G(false, att1 + (size_t)SL_*DV_, W2mid, kqv2 + (size_t)SL_*384,
          SEG_, 384, DV_, DV_, 384, 384,
          (long long)H_*L_*DV_, (long long)L_*DV_, 0, (long long)64*384,
          (long long)H_*L_*384, (long long)L_*384, H_, B_*H_);
        G(false, att1 + (size_t)(SL_+SEG_)*DV_, W2se, kqv2 + (size_t)(SL_+SEG_)*384,
          SL_, 384, DV_, DV_, 384, 384,
          (long long)H_*L_*DV_, (long long)L_*DV_, 0, (long long)64*384,
          (long long)H_*L_*384, (long long)L_*384, H_, B_*H_);

        // attention 2: fused flash, skips rows [0,SL), writes a2r/a2er directly
        flash_k<128,true><<<dim3(L_/128 - 1, B_*H_), 256, SM128>>>(
            kqv2, 384, (long long)L_*384, 128, 0, 256, a2r, a2er);

        // out segment (split-K x2)
        G(false, a2r, Wout, out + (size_t)seg*SEG_*D_, SEG_, D_, 2048, 2048, D_, D_,
          (long long)SEG_*2048, 0, 0, 0, (long long)S_*D_, 0, 1, B_, 2);
        // next state (split-K x8)
        G(false, a2er, Wout_st, stn, SL_, D_, 2048, 2048, D_, D_,
          (long long)SL_*2048, 0, 0, 0, (long long)SL_*D_, 0, 1, B_, 8);
    }

    int st_elems = B_ * SL_ * D_;
    if (out_size >= B_*S_*D_ + st_elems) {
        copy_f<<<(st_elems + 255)/256, 256>>>(out + (size_t)B_*S_*D_, stA, st_elems);
    }
}